// round 5
// baseline (speedup 1.0000x reference)
#include <cuda_runtime.h>
#include <cuda_bf16.h>
#include <stdint.h>

// Problem constants (fixed shapes)
#define BATCH 8
#define HH 1024
#define WW 1024
#define HW (HH * WW)

#define TILE 32
#define NTHREADS 256

#define HALO_Y 7            // search radius 5 + patch radius 2
#define HALO_RGB 5
#define SY_DIM 46           // 32 + 2*7
#define SY_STRIDE 48
#define SRGB_DIM 42         // 32 + 2*5
#define SRGB_STRIDE 45      // odd -> conflict-free scalar pattern (sb)
#define CS_COLS 36          // columns j in [-2, 34)
#define CS_STRIDE 40        // multiple of 4 -> LDS.128-able in stage C

#define N_SY (SY_DIM * SY_DIM)
#define N_SRGB (SRGB_DIM * SRGB_DIM)
#define N_CS_TASKS 252      // 7 vertical runs x 36 columns

// exp(-sqrt(S)/ (h+1e-6)) = exp2( sqrt(S) * (-log2(e)/(h+1e-6)) )
#define NEG_INVH_LOG2E (-1.4426950408889634f / (1.0f + 1e-6f))

__device__ __forceinline__ float rsqrt_approx(float x) {
    float r;
    asm("rsqrt.approx.f32 %0, %1;" : "=f"(r) : "f"(x));
    return r;
}
__device__ __forceinline__ float exp2_approx(float x) {
    float r;
    asm("ex2.approx.f32 %0, %1;" : "=f"(r) : "f"(x));
    return r;
}
__device__ __forceinline__ unsigned long long pack2(float lo, float hi) {
    unsigned long long p;
    asm("mov.b64 %0, {%1, %2};" : "=l"(p) : "f"(lo), "f"(hi));
    return p;
}
__device__ __forceinline__ void fma_f32x2(unsigned long long& d,
                                          unsigned long long a,
                                          unsigned long long b) {
    asm("fma.rn.f32x2 %0, %1, %2, %0;" : "+l"(d) : "l"(a), "l"(b));
}

// Vertical run start rows: 7 runs of length 5 covering rows 0..31 (overlaps
// write identical values -> benign).
__device__ __constant__ int c_i0[7] = {0, 5, 10, 15, 20, 24, 27};

__global__ __launch_bounds__(NTHREADS, 3)
void nlm_kernel(const float* __restrict__ rgb, float* __restrict__ out) {
    __shared__ float sy[SY_DIM * SY_STRIDE];
    __shared__ __align__(8) float srg[SRGB_DIM * SRGB_STRIDE * 2]; // (r,g) pairs
    __shared__ float sb[SRGB_DIM * SRGB_STRIDE];
    __shared__ __align__(16) float cs[2][TILE * CS_STRIDE];  // double-buffered

    const int tid = threadIdx.x;
    const int b   = blockIdx.z;
    const int ty0 = blockIdx.y * TILE;
    const int tx0 = blockIdx.x * TILE;

    const float* base = rgb + (size_t)b * 3 * HW;

    // ---- Fill luminance tile (halo 7) ----
    for (int idx = tid; idx < N_SY; idx += NTHREADS) {
        int r = idx / SY_DIM, c = idx - r * SY_DIM;
        int gy = (ty0 + r - HALO_Y) & (HH - 1);
        int gx = (tx0 + c - HALO_Y) & (WW - 1);
        size_t o = (size_t)gy * WW + gx;
        sy[r * SY_STRIDE + c] =
            (base[o] + base[o + HW] + base[o + 2 * HW]) * (1.0f / 3.0f);
    }

    // ---- Fill rgb tiles (halo 5): (r,g) interleaved pairs + scalar b ----
    for (int idx = tid; idx < N_SRGB; idx += NTHREADS) {
        int r = idx / SRGB_DIM, c = idx - r * SRGB_DIM;
        int gy = (ty0 + r - HALO_RGB) & (HH - 1);
        int gx = (tx0 + c - HALO_RGB) & (WW - 1);
        size_t o = (size_t)gy * WW + gx;
        int so = r * SRGB_STRIDE + c;
        srg[so * 2]     = base[o];
        srg[so * 2 + 1] = base[o + HW];
        sb[so]          = base[o + 2 * HW];
    }
    __syncthreads();

    // ---- Stage-AB task: vertical run of 5 cs outputs in one column ----
    const int tk   = (tid < N_CS_TASKS) ? tid : 0;
    const int col  = tk % CS_COLS;           // cs column (image col = col-2)
    const int run  = tk / CS_COLS;
    const int i0   = c_i0[run];

    // Center-y values for this thread's 9 d2 rows — FIXED across all shifts.
    float yc[9];
#pragma unroll
    for (int u = 0; u < 9; u++)
        yc[u] = sy[(i0 + 5 + u) * SY_STRIDE + (col + 5)];

    // ---- Stage-C task: 4 consecutive output columns in one row ----
    const int ci  = tid >> 3;        // output row 0..31
    const int cj0 = (tid & 7) * 4;   // output col start

    unsigned long long accRG[4] = {0ull, 0ull, 0ull, 0ull};
    float accB[4] = {0.f, 0.f, 0.f, 0.f};
    float wsum[4] = {0.f, 0.f, 0.f, 0.f};

    int buf = 0;
#pragma unroll 1
    for (int dx = -5; dx <= 5; dx++) {
        // Shifted-y column pointer for this dx (fixed within the dy loop).
        const float* ycol = &sy[col + 5 - dx];

        // Preload the 9-row shifted-y window for dy = -5:
        float ysh[9];
#pragma unroll
        for (int u = 0; u < 9; u++)
            ysh[u] = ycol[(i0 + 10 + u) * SY_STRIDE];

#pragma unroll
        for (int dy = -5; dy <= 5; dy++) {
            // ---- Stage AB: fused d2 + vertical 5-sum -> cs[buf] ----
            if (tid < N_CS_TASKS) {
                float d[9];
#pragma unroll
                for (int u = 0; u < 9; u++) {
                    float dd = yc[u] - ysh[u];
                    d[u] = dd * dd;
                }
                float s = ((d[0] + d[1]) + (d[2] + d[3])) + d[4];
                float* cp = &cs[buf][i0 * CS_STRIDE + col];
                cp[0 * CS_STRIDE] = s;
#pragma unroll
                for (int v = 1; v < 5; v++) {
                    s += d[v + 4] - d[v - 1];
                    cp[v * CS_STRIDE] = s;
                }
            }
            __syncthreads();

            // ---- Stage C: horizontal sliding 5-sum + weight + accumulate ----
            const float4* cq =
                (const float4*)&cs[buf][ci * CS_STRIDE + cj0];
            float4 v0 = cq[0];
            float4 v1 = cq[1];

            float S0 = ((v0.x + v0.y) + (v0.z + v0.w)) + v1.x;
            float S1 = S0 + (v1.y - v0.x);
            float S2 = S1 + (v1.z - v0.y);
            float S3 = S2 + (v1.w - v0.z);

            const int sobase =
                (ci - dy + HALO_RGB) * SRGB_STRIDE + (cj0 - dx + HALO_RGB);
            float S[4] = {S0, S1, S2, S3};
#pragma unroll
            for (int m = 0; m < 4; m++) {
                float t  = fmaxf(S[m], 1e-20f);
                float sq = S[m] * rsqrt_approx(t);            // ~= sqrt(S)
                float w  = exp2_approx(sq * NEG_INVH_LOG2E);  // exp(-sqrt(S)/h')
                int so = sobase + m;
                unsigned long long rg =
                    *(const unsigned long long*)&srg[so * 2];
                fma_f32x2(accRG[m], rg, pack2(w, w));
                accB[m] = fmaf(sb[so], w, accB[m]);
                wsum[m] += w;
            }
            buf ^= 1;
            // cs is double-buffered; the barrier above orders this
            // iteration's reads against writes two iterations out.

            // ---- Slide the shifted-y window down one row (for dy+1) ----
            if (dy < 5) {
#pragma unroll
                for (int u = 8; u >= 1; u--) ysh[u] = ysh[u - 1];
                ysh[0] = ycol[(i0 + 4 - dy) * SY_STRIDE];
            }
        }
    }

    // ---- Write out: out = acc / wsum, float4 per channel ----
    float* outb = out + (size_t)b * 3 * HW;
    size_t o = (size_t)(ty0 + ci) * WW + (tx0 + cj0);
    float aR[4], aG[4];
#pragma unroll
    for (int m = 0; m < 4; m++) {
        float lo, hi;
        asm("mov.b64 {%0, %1}, %2;" : "=f"(lo), "=f"(hi) : "l"(accRG[m]));
        aR[m] = lo; aG[m] = hi;
    }
    float inv0 = 1.0f / wsum[0], inv1 = 1.0f / wsum[1];
    float inv2 = 1.0f / wsum[2], inv3 = 1.0f / wsum[3];
    *(float4*)&outb[o] =
        make_float4(aR[0] * inv0, aR[1] * inv1, aR[2] * inv2, aR[3] * inv3);
    *(float4*)&outb[o + HW] =
        make_float4(aG[0] * inv0, aG[1] * inv1, aG[2] * inv2, aG[3] * inv3);
    *(float4*)&outb[o + 2 * HW] =
        make_float4(accB[0] * inv0, accB[1] * inv1, accB[2] * inv2, accB[3] * inv3);
}

extern "C" void kernel_launch(void* const* d_in, const int* in_sizes, int n_in,
                              void* d_out, int out_size) {
    const float* rgb = (const float*)d_in[0];
    float* out = (float*)d_out;
    dim3 grid(WW / TILE, HH / TILE, BATCH);
    nlm_kernel<<<grid, NTHREADS>>>(rgb, out);
}

// round 6
// speedup vs baseline: 1.1213x; 1.1213x over previous
#include <cuda_runtime.h>
#include <cuda_fp16.h>
#include <stdint.h>

// Problem constants (fixed shapes)
#define BATCH 8
#define HH 1024
#define WW 1024
#define HW (HH * WW)

#define TILE 32
#define NTHREADS 256

#define HALO_Y 7            // search radius 5 + patch radius 2
#define HALO_RGB 5
#define SY_DIM 46           // 32 + 2*7
#define SY_STRIDE 48
#define SRGB_DIM 42         // 32 + 2*5
#define SRGB_STRIDE 45      // odd -> conflict-free for stage-C pattern
#define CS_COLS 36          // columns j in [-2, 34)
#define CS_STRIDE 40        // multiple of 4 -> LDS.128-able in stage C

#define N_SY (SY_DIM * SY_DIM)
#define N_SRGB (SRGB_DIM * SRGB_DIM)
#define N_CS_TASKS 252      // 7 vertical runs x 36 columns

// exp(-sqrt(S)/(h+1e-6)) = exp2( sqrt(S) * (-log2(e)/(h+1e-6)) )
#define NEG_INVH_LOG2E (-1.4426950408889634f / (1.0f + 1e-6f))

__device__ __forceinline__ float rsqrt_approx(float x) {
    float r;
    asm("rsqrt.approx.f32 %0, %1;" : "=f"(r) : "f"(x));
    return r;
}
__device__ __forceinline__ float exp2_approx(float x) {
    float r;
    asm("ex2.approx.f32 %0, %1;" : "=f"(r) : "f"(x));
    return r;
}

// Vertical run start rows: 7 runs of length 5 covering rows 0..31 (overlaps
// write identical values -> benign).
__device__ __constant__ int c_i0[7] = {0, 5, 10, 15, 20, 24, 27};

__global__ __launch_bounds__(NTHREADS, 3)
void nlm_kernel(const float* __restrict__ rgb, float* __restrict__ out) {
    __shared__ float sy[SY_DIM * SY_STRIDE];
    __shared__ __half2 srg[SRGB_DIM * SRGB_STRIDE];  // (r,g) packed fp16x2
    __shared__ float sb[SRGB_DIM * SRGB_STRIDE];     // b exact fp32
    __shared__ __align__(16) float cs[2][TILE * CS_STRIDE];  // double-buffered

    const int tid = threadIdx.x;
    const int b   = blockIdx.z;
    const int ty0 = blockIdx.y * TILE;
    const int tx0 = blockIdx.x * TILE;

    const float* base = rgb + (size_t)b * 3 * HW;

    // ---- Fill luminance tile (halo 7) ----
    for (int idx = tid; idx < N_SY; idx += NTHREADS) {
        int r = idx / SY_DIM, c = idx - r * SY_DIM;
        int gy = (ty0 + r - HALO_Y) & (HH - 1);
        int gx = (tx0 + c - HALO_Y) & (WW - 1);
        size_t o = (size_t)gy * WW + gx;
        sy[r * SY_STRIDE + c] =
            (base[o] + base[o + HW] + base[o + 2 * HW]) * (1.0f / 3.0f);
    }

    // ---- Fill rgb tiles (halo 5): (r,g) as half2, b as fp32 ----
    for (int idx = tid; idx < N_SRGB; idx += NTHREADS) {
        int r = idx / SRGB_DIM, c = idx - r * SRGB_DIM;
        int gy = (ty0 + r - HALO_RGB) & (HH - 1);
        int gx = (tx0 + c - HALO_RGB) & (WW - 1);
        size_t o = (size_t)gy * WW + gx;
        int so = r * SRGB_STRIDE + c;
        srg[so] = __floats2half2_rn(base[o], base[o + HW]);
        sb[so]  = base[o + 2 * HW];
    }
    __syncthreads();

    // ---- Stage-AB task: vertical run of 5 cs outputs in one column ----
    const int tk   = (tid < N_CS_TASKS) ? tid : 0;
    const int col  = tk % CS_COLS;           // cs column (image col = col-2)
    const int run  = tk / CS_COLS;
    const int i0   = c_i0[run];

    // Center-y values for this thread's 9 d2 rows — FIXED across all shifts.
    float yc[9];
#pragma unroll
    for (int u = 0; u < 9; u++)
        yc[u] = sy[(i0 + 5 + u) * SY_STRIDE + (col + 5)];

    // ---- Stage-C task: 4 consecutive output columns in one row ----
    const int ci  = tid >> 3;        // output row 0..31
    const int cj0 = (tid & 7) * 4;   // output col start

    float accR[4] = {0.f, 0.f, 0.f, 0.f};
    float accG[4] = {0.f, 0.f, 0.f, 0.f};
    float accB[4] = {0.f, 0.f, 0.f, 0.f};
    float wsum[4] = {0.f, 0.f, 0.f, 0.f};

    int buf = 0;
#pragma unroll 1
    for (int dx = -5; dx <= 5; dx++) {
        // Shifted-y column pointer for this dx (fixed within the dy loop).
        const float* ycol = &sy[col + 5 - dx];

        // Preload the 9-row shifted-y window for dy = -5:
        float ysh[9];
#pragma unroll
        for (int u = 0; u < 9; u++)
            ysh[u] = ycol[(i0 + 10 + u) * SY_STRIDE];

#pragma unroll
        for (int dy = -5; dy <= 5; dy++) {
            // ---- Stage AB: fused d2 + vertical 5-sum -> cs[buf] ----
            if (tid < N_CS_TASKS) {
                float d[9];
#pragma unroll
                for (int u = 0; u < 9; u++) {
                    float dd = yc[u] - ysh[u];
                    d[u] = dd * dd;
                }
                float s = ((d[0] + d[1]) + (d[2] + d[3])) + d[4];
                float* cp = &cs[buf][i0 * CS_STRIDE + col];
                cp[0 * CS_STRIDE] = s;
#pragma unroll
                for (int v = 1; v < 5; v++) {
                    s += d[v + 4] - d[v - 1];
                    cp[v * CS_STRIDE] = s;
                }
            }
            __syncthreads();

            // ---- Stage C: horizontal sliding 5-sum + weight + accumulate ----
            const float4* cq =
                (const float4*)&cs[buf][ci * CS_STRIDE + cj0];
            float4 v0 = cq[0];
            float4 v1 = cq[1];

            float S0 = ((v0.x + v0.y) + (v0.z + v0.w)) + v1.x;
            float S1 = S0 + (v1.y - v0.x);
            float S2 = S1 + (v1.z - v0.y);
            float S3 = S2 + (v1.w - v0.z);

            const int sobase =
                (ci - dy + HALO_RGB) * SRGB_STRIDE + (cj0 - dx + HALO_RGB);
            float S[4] = {S0, S1, S2, S3};
#pragma unroll
            for (int m = 0; m < 4; m++) {
                float t  = fmaxf(S[m], 1e-20f);
                float sq = S[m] * rsqrt_approx(t);            // ~= sqrt(S)
                float w  = exp2_approx(sq * NEG_INVH_LOG2E);  // exp(-sqrt(S)/h')
                int so = sobase + m;
                float2 rg = __half22float2(srg[so]);
                accR[m] = fmaf(rg.x, w, accR[m]);
                accG[m] = fmaf(rg.y, w, accG[m]);
                accB[m] = fmaf(sb[so], w, accB[m]);
                wsum[m] += w;
            }
            buf ^= 1;
            // cs is double-buffered; the barrier above orders this
            // iteration's reads against writes two iterations out.

            // ---- Slide the shifted-y window down one row (for dy+1) ----
            if (dy < 5) {
#pragma unroll
                for (int u = 8; u >= 1; u--) ysh[u] = ysh[u - 1];
                ysh[0] = ycol[(i0 + 4 - dy) * SY_STRIDE];
            }
        }
    }

    // ---- Write out: out = acc / wsum, float4 per channel ----
    float* outb = out + (size_t)b * 3 * HW;
    size_t o = (size_t)(ty0 + ci) * WW + (tx0 + cj0);
    float inv0 = 1.0f / wsum[0], inv1 = 1.0f / wsum[1];
    float inv2 = 1.0f / wsum[2], inv3 = 1.0f / wsum[3];
    *(float4*)&outb[o] =
        make_float4(accR[0] * inv0, accR[1] * inv1, accR[2] * inv2, accR[3] * inv3);
    *(float4*)&outb[o + HW] =
        make_float4(accG[0] * inv0, accG[1] * inv1, accG[2] * inv2, accG[3] * inv3);
    *(float4*)&outb[o + 2 * HW] =
        make_float4(accB[0] * inv0, accB[1] * inv1, accB[2] * inv2, accB[3] * inv3);
}

extern "C" void kernel_launch(void* const* d_in, const int* in_sizes, int n_in,
                              void* d_out, int out_size) {
    const float* rgb = (const float*)d_in[0];
    float* out = (float*)d_out;
    dim3 grid(WW / TILE, HH / TILE, BATCH);
    nlm_kernel<<<grid, NTHREADS>>>(rgb, out);
}

// round 7
// speedup vs baseline: 1.1673x; 1.0410x over previous
#include <cuda_runtime.h>
#include <cuda_fp16.h>
#include <stdint.h>

// Problem constants (fixed shapes)
#define BATCH 8
#define HH 1024
#define WW 1024
#define HW (HH * WW)

#define TILE 32
#define NTHREADS 256

#define HALO_Y 7            // search radius 5 + patch radius 2
#define HALO_RGB 5
#define SY_DIM 46           // 32 + 2*7
#define SY_STRIDE 48
#define SRGB_DIM 42         // 32 + 2*5
#define SRGB_STRIDE 45      // odd -> conflict-free for stage-C pattern
#define CS_COLS 36          // columns j in [-2, 34)
#define CS_STRIDE 40        // multiple of 4 -> LDS.128-able in stage C

#define N_SY (SY_DIM * SY_DIM)
#define N_SRGB (SRGB_DIM * SRGB_DIM)
#define N_CS_TASKS 252      // 7 vertical runs x 36 columns

// w = exp(-sqrt(S)/(h+1e-6)) = exp2(-sqrt(c^2 * S)), c = log2(e)/(h+1e-6).
// We pre-scale y by c so the S reaching stage C is already c^2-scaled.
#define KSCALE 1.4426935981939225f

__device__ __forceinline__ float sqrt_abs_approx(float x) {
    float r;
    asm("sqrt.approx.f32 %0, %1;" : "=f"(r) : "f"(fabsf(x)));
    return r;
}
__device__ __forceinline__ float exp2_neg_approx(float x) {  // exp2(-x)
    float r;
    float nx = -x;
    asm("ex2.approx.f32 %0, %1;" : "=f"(r) : "f"(nx));
    return r;
}

// Vertical run start rows: 7 runs of length 5 covering rows 0..31 (overlaps
// write identical values -> benign).
__device__ __constant__ int c_i0[7] = {0, 5, 10, 15, 20, 24, 27};

__global__ __launch_bounds__(NTHREADS, 3)
void nlm_kernel(const float* __restrict__ rgb, float* __restrict__ out) {
    __shared__ float sy[SY_DIM * SY_STRIDE];
    __shared__ __half2 srg[SRGB_DIM * SRGB_STRIDE];  // (r,g) packed fp16x2
    __shared__ float sb[SRGB_DIM * SRGB_STRIDE];     // b exact fp32
    __shared__ __align__(16) float cs[2][TILE * CS_STRIDE];  // double-buffered

    const int tid = threadIdx.x;
    const int b   = blockIdx.z;
    const int ty0 = blockIdx.y * TILE;
    const int tx0 = blockIdx.x * TILE;

    const float* base = rgb + (size_t)b * 3 * HW;

    // ---- Fill luminance tile (halo 7) ----
    for (int idx = tid; idx < N_SY; idx += NTHREADS) {
        int r = idx / SY_DIM, c = idx - r * SY_DIM;
        int gy = (ty0 + r - HALO_Y) & (HH - 1);
        int gx = (tx0 + c - HALO_Y) & (WW - 1);
        size_t o = (size_t)gy * WW + gx;
        sy[r * SY_STRIDE + c] =
            (base[o] + base[o + HW] + base[o + 2 * HW]) * (1.0f / 3.0f);
    }

    // ---- Fill rgb tiles (halo 5): (r,g) as half2, b as fp32 ----
    for (int idx = tid; idx < N_SRGB; idx += NTHREADS) {
        int r = idx / SRGB_DIM, c = idx - r * SRGB_DIM;
        int gy = (ty0 + r - HALO_RGB) & (HH - 1);
        int gx = (tx0 + c - HALO_RGB) & (WW - 1);
        size_t o = (size_t)gy * WW + gx;
        int so = r * SRGB_STRIDE + c;
        srg[so] = __floats2half2_rn(base[o], base[o + HW]);
        sb[so]  = base[o + 2 * HW];
    }
    __syncthreads();

    // ---- Stage-AB task: vertical run of 5 cs outputs in one column ----
    const int tk   = (tid < N_CS_TASKS) ? tid : 0;
    const int col  = tk % CS_COLS;           // cs column (image col = col-2)
    const int run  = tk / CS_COLS;
    const int i0   = c_i0[run];

    // Center-y values (pre-scaled by KSCALE) — FIXED across all shifts.
    float yc[9];
#pragma unroll
    for (int u = 0; u < 9; u++)
        yc[u] = KSCALE * sy[(i0 + 5 + u) * SY_STRIDE + (col + 5)];

    // ---- Stage-C task: 4 consecutive output columns in one row ----
    const int ci  = tid >> 3;        // output row 0..31
    const int cj0 = (tid & 7) * 4;   // output col start

    float accR[4] = {0.f, 0.f, 0.f, 0.f};
    float accG[4] = {0.f, 0.f, 0.f, 0.f};
    float accB[4] = {0.f, 0.f, 0.f, 0.f};
    float wsum[4] = {0.f, 0.f, 0.f, 0.f};

    int buf = 0;
#pragma unroll 1
    for (int dx = -5; dx <= 5; dx++) {
        // Shifted-y column pointer for this dx (fixed within the dy loop).
        const float* ycol = &sy[col + 5 - dx];

        // Preload the 9-row shifted-y window (scaled) for dy = -5:
        float ysh[9];
#pragma unroll
        for (int u = 0; u < 9; u++)
            ysh[u] = KSCALE * ycol[(i0 + 10 + u) * SY_STRIDE];

#pragma unroll
        for (int dy = -5; dy <= 5; dy++) {
            // ---- Stage AB: fused d2 + vertical 5-sum -> cs[buf] ----
            if (tid < N_CS_TASKS) {
                float d[9];
#pragma unroll
                for (int u = 0; u < 9; u++) {
                    float dd = yc[u] - ysh[u];
                    d[u] = dd * dd;
                }
                float s = ((d[0] + d[1]) + (d[2] + d[3])) + d[4];
                float* cp = &cs[buf][i0 * CS_STRIDE + col];
                cp[0 * CS_STRIDE] = s;
#pragma unroll
                for (int v = 1; v < 5; v++) {
                    s += d[v + 4] - d[v - 1];
                    cp[v * CS_STRIDE] = s;
                }
            }
            __syncthreads();

            // ---- Stage C: horizontal sliding 5-sum + weight + accumulate ----
            const float4* cq =
                (const float4*)&cs[buf][ci * CS_STRIDE + cj0];
            float4 v0 = cq[0];
            float4 v1 = cq[1];

            float S0 = ((v0.x + v0.y) + (v0.z + v0.w)) + v1.x;
            float S1 = S0 + (v1.y - v0.x);
            float S2 = S1 + (v1.z - v0.y);
            float S3 = S2 + (v1.w - v0.z);

            const int sobase =
                (ci - dy + HALO_RGB) * SRGB_STRIDE + (cj0 - dx + HALO_RGB);
            float S[4] = {S0, S1, S2, S3};
#pragma unroll
            for (int m = 0; m < 4; m++) {
                float sq = sqrt_abs_approx(S[m]);   // = sqrt(c^2 * S)
                float w  = exp2_neg_approx(sq);     // = exp(-sqrt(S)/h')
                int so = sobase + m;
                float2 rg = __half22float2(srg[so]);
                accR[m] = fmaf(rg.x, w, accR[m]);
                accG[m] = fmaf(rg.y, w, accG[m]);
                accB[m] = fmaf(sb[so], w, accB[m]);
                wsum[m] += w;
            }
            buf ^= 1;
            // cs is double-buffered; the barrier above orders this
            // iteration's reads against writes two iterations out.

            // ---- Slide the shifted-y window down one row (for dy+1) ----
            if (dy < 5) {
#pragma unroll
                for (int u = 8; u >= 1; u--) ysh[u] = ysh[u - 1];
                ysh[0] = KSCALE * ycol[(i0 + 4 - dy) * SY_STRIDE];
            }
        }
    }

    // ---- Write out: out = acc / wsum, float4 per channel ----
    float* outb = out + (size_t)b * 3 * HW;
    size_t o = (size_t)(ty0 + ci) * WW + (tx0 + cj0);
    float inv0 = 1.0f / wsum[0], inv1 = 1.0f / wsum[1];
    float inv2 = 1.0f / wsum[2], inv3 = 1.0f / wsum[3];
    *(float4*)&outb[o] =
        make_float4(accR[0] * inv0, accR[1] * inv1, accR[2] * inv2, accR[3] * inv3);
    *(float4*)&outb[o + HW] =
        make_float4(accG[0] * inv0, accG[1] * inv1, accG[2] * inv2, accG[3] * inv3);
    *(float4*)&outb[o + 2 * HW] =
        make_float4(accB[0] * inv0, accB[1] * inv1, accB[2] * inv2, accB[3] * inv3);
}

extern "C" void kernel_launch(void* const* d_in, const int* in_sizes, int n_in,
                              void* d_out, int out_size) {
    const float* rgb = (const float*)d_in[0];
    float* out = (float*)d_out;
    dim3 grid(WW / TILE, HH / TILE, BATCH);
    nlm_kernel<<<grid, NTHREADS>>>(rgb, out);
}

// round 8
// speedup vs baseline: 1.1716x; 1.0037x over previous
#include <cuda_runtime.h>
#include <cuda_fp16.h>
#include <stdint.h>

// Problem constants (fixed shapes)
#define BATCH 8
#define HH 1024
#define WW 1024
#define HW (HH * WW)

#define TILE 32
#define NTHREADS 256

#define HALO_Y 7            // search radius 5 + patch radius 2
#define HALO_RGB 5
#define SY_DIM 46           // 32 + 2*7
#define SY_STRIDE 48
#define SRGB_DIM 42         // 32 + 2*5
#define SRGB_STRIDE 45      // odd -> conflict-free for stage-C pattern
#define CS_COLS 36          // columns j in [-2, 34)
#define CS_STRIDE 40        // multiple of 4 -> LDS.128-able in stage C

#define N_SY (SY_DIM * SY_DIM)
#define N_SRGB (SRGB_DIM * SRGB_DIM)
#define N_CS_TASKS 252      // 7 vertical runs x 36 columns

// w = exp(-sqrt(S)/(h+1e-6)) = exp2(-sqrt(c^2 * S)), c = log2(e)/(h+1e-6).
// We pre-scale y by c so the S reaching stage C is already c^2-scaled.
#define KSCALE 1.4426935981939225f

__device__ __forceinline__ float sqrt_abs_approx(float x) {
    float r;
    asm("sqrt.approx.f32 %0, %1;" : "=f"(r) : "f"(fabsf(x)));
    return r;
}
__device__ __forceinline__ float exp2_neg_approx(float x) {  // exp2(-x)
    float r;
    float nx = -x;
    asm("ex2.approx.f32 %0, %1;" : "=f"(r) : "f"(nx));
    return r;
}

// Vertical run start rows: 7 runs of length 5 covering rows 0..31 (overlaps
// write identical values -> benign).
__device__ __constant__ int c_i0[7] = {0, 5, 10, 15, 20, 24, 27};

__global__ __launch_bounds__(NTHREADS, 3)
void nlm_kernel(const float* __restrict__ rgb, float* __restrict__ out) {
    __shared__ float sy[SY_DIM * SY_STRIDE];
    __shared__ __half2 srg[SRGB_DIM * SRGB_STRIDE];  // (r,g) packed fp16x2
    __shared__ float sb[SRGB_DIM * SRGB_STRIDE];     // b exact fp32
    __shared__ __align__(16) float cs[2][TILE * CS_STRIDE];  // double-buffered

    const int tid = threadIdx.x;
    const int b   = blockIdx.z;
    const int ty0 = blockIdx.y * TILE;
    const int tx0 = blockIdx.x * TILE;

    const float* base = rgb + (size_t)b * 3 * HW;

    // ---- Fill luminance tile (halo 7) ----
    for (int idx = tid; idx < N_SY; idx += NTHREADS) {
        int r = idx / SY_DIM, c = idx - r * SY_DIM;
        int gy = (ty0 + r - HALO_Y) & (HH - 1);
        int gx = (tx0 + c - HALO_Y) & (WW - 1);
        size_t o = (size_t)gy * WW + gx;
        sy[r * SY_STRIDE + c] =
            (base[o] + base[o + HW] + base[o + 2 * HW]) * (1.0f / 3.0f);
    }

    // ---- Fill rgb tiles (halo 5): (r,g) as half2, b as fp32 ----
    for (int idx = tid; idx < N_SRGB; idx += NTHREADS) {
        int r = idx / SRGB_DIM, c = idx - r * SRGB_DIM;
        int gy = (ty0 + r - HALO_RGB) & (HH - 1);
        int gx = (tx0 + c - HALO_RGB) & (WW - 1);
        size_t o = (size_t)gy * WW + gx;
        int so = r * SRGB_STRIDE + c;
        srg[so] = __floats2half2_rn(base[o], base[o + HW]);
        sb[so]  = base[o + 2 * HW];
    }
    __syncthreads();

    // ---- Stage-AB task: vertical run of 5 cs outputs in one column ----
    const int tk   = (tid < N_CS_TASKS) ? tid : 0;
    const int col  = tk % CS_COLS;           // cs column (image col = col-2)
    const int run  = tk / CS_COLS;
    const int i0   = c_i0[run];

    // Center-y values (pre-scaled by KSCALE) — FIXED across all shifts.
    float yc[9];
#pragma unroll
    for (int u = 0; u < 9; u++)
        yc[u] = KSCALE * sy[(i0 + 5 + u) * SY_STRIDE + (col + 5)];

    // ---- Stage-C task: 4 consecutive output columns in one row ----
    const int ci  = tid >> 3;        // output row 0..31
    const int cj0 = (tid & 7) * 4;   // output col start

    float accR[4] = {0.f, 0.f, 0.f, 0.f};
    float accG[4] = {0.f, 0.f, 0.f, 0.f};
    float accB[4] = {0.f, 0.f, 0.f, 0.f};
    float wsum[4] = {0.f, 0.f, 0.f, 0.f};

    int buf = 0;
#pragma unroll 1
    for (int dx = -5; dx <= 5; dx++) {
        // Shifted-y column pointer for this dx (fixed within the dy loop).
        const float* ycol = &sy[col + 5 - dx];

        // Preload the 9-row shifted-y window (scaled) for dy = -5:
        float ysh[9];
#pragma unroll
        for (int u = 0; u < 9; u++)
            ysh[u] = KSCALE * ycol[(i0 + 10 + u) * SY_STRIDE];

#pragma unroll
        for (int dy = -5; dy <= 5; dy++) {
            // ---- Stage AB: fused d2 + vertical 5-sum -> cs[buf] ----
            if (tid < N_CS_TASKS) {
                float d[9];
#pragma unroll
                for (int u = 0; u < 9; u++) {
                    float dd = yc[u] - ysh[u];
                    d[u] = dd * dd;
                }
                float s = ((d[0] + d[1]) + (d[2] + d[3])) + d[4];
                float* cp = &cs[buf][i0 * CS_STRIDE + col];
                cp[0 * CS_STRIDE] = s;
#pragma unroll
                for (int v = 1; v < 5; v++) {
                    s += d[v + 4] - d[v - 1];
                    cp[v * CS_STRIDE] = s;
                }
            }
            __syncthreads();

            // ---- Stage C: horizontal sliding 5-sum + weight + accumulate ----
            const float4* cq =
                (const float4*)&cs[buf][ci * CS_STRIDE + cj0];
            float4 v0 = cq[0];
            float4 v1 = cq[1];

            float S0 = ((v0.x + v0.y) + (v0.z + v0.w)) + v1.x;
            float S1 = S0 + (v1.y - v0.x);
            float S2 = S1 + (v1.z - v0.y);
            float S3 = S2 + (v1.w - v0.z);

            const int sobase =
                (ci - dy + HALO_RGB) * SRGB_STRIDE + (cj0 - dx + HALO_RGB);
            float S[4] = {S0, S1, S2, S3};
#pragma unroll
            for (int m = 0; m < 4; m++) {
                float sq = sqrt_abs_approx(S[m]);   // = sqrt(c^2 * S)
                float w  = exp2_neg_approx(sq);     // = exp(-sqrt(S)/h')
                int so = sobase + m;
                float2 rg = __half22float2(srg[so]);
                accR[m] = fmaf(rg.x, w, accR[m]);
                accG[m] = fmaf(rg.y, w, accG[m]);
                accB[m] = fmaf(sb[so], w, accB[m]);
                wsum[m] += w;
            }
            buf ^= 1;
            // cs is double-buffered; the barrier above orders this
            // iteration's reads against writes two iterations out.

            // ---- Slide the shifted-y window down one row (for dy+1) ----
            if (dy < 5) {
#pragma unroll
                for (int u = 8; u >= 1; u--) ysh[u] = ysh[u - 1];
                ysh[0] = KSCALE * ycol[(i0 + 4 - dy) * SY_STRIDE];
            }
        }
    }

    // ---- Write out: out = acc / wsum, float4 per channel ----
    float* outb = out + (size_t)b * 3 * HW;
    size_t o = (size_t)(ty0 + ci) * WW + (tx0 + cj0);
    float inv0 = 1.0f / wsum[0], inv1 = 1.0f / wsum[1];
    float inv2 = 1.0f / wsum[2], inv3 = 1.0f / wsum[3];
    *(float4*)&outb[o] =
        make_float4(accR[0] * inv0, accR[1] * inv1, accR[2] * inv2, accR[3] * inv3);
    *(float4*)&outb[o + HW] =
        make_float4(accG[0] * inv0, accG[1] * inv1, accG[2] * inv2, accG[3] * inv3);
    *(float4*)&outb[o + 2 * HW] =
        make_float4(accB[0] * inv0, accB[1] * inv1, accB[2] * inv2, accB[3] * inv3);
}

extern "C" void kernel_launch(void* const* d_in, const int* in_sizes, int n_in,
                              void* d_out, int out_size) {
    const float* rgb = (const float*)d_in[0];
    float* out = (float*)d_out;
    dim3 grid(WW / TILE, HH / TILE, BATCH);
    nlm_kernel<<<grid, NTHREADS>>>(rgb, out);
}